// round 1
// baseline (speedup 1.0000x reference)
#include <cuda_runtime.h>
#include <cstdint>

// ---------------------------------------------------------------------------
// LSTM autoencoder: 4 layers, B=64, T=1024, H in {256,128,256,256}.
// Strategy per layer:
//   1) sgemm_bias: zx[b][t][4H] = x[b][t][:] @ W + b        (parallel GEMM)
//   2) lstm_rec:   persistent 128-CTA kernel, 8 batch groups x 16 col CTAs,
//                  flag-synced per step within each batch group.
// All fp32 (matches reference numerics; rel_err should be ~1e-6).
// ---------------------------------------------------------------------------

#define T_STEPS 1024
#define BATCH   64

// Scratch (device globals: allocation-free rule)
__device__ float g_zx[67108864];    // up to [B*T][4*256] = 64*1024*1024 floats (256 MB)
__device__ float g_bufA[16777216];  // [B][T][256]
__device__ float g_bufB[8388608];   // [B][T][128]
__device__ int   g_flags[8 * T_STEPS]; // [G][T] step-completion counters

// ---------------------------------------------------------------------------
// GEMM: C[m][n] = sum_k A[m][k]*B[k][n] + bias[n]
// BM=128, BN=64, BK=16, 256 threads, 8x4 microtile. M%128==0, N%64==0, K%16==0.
// ---------------------------------------------------------------------------
__global__ __launch_bounds__(256) void sgemm_bias(
    const float* __restrict__ A, const float* __restrict__ B,
    const float* __restrict__ bias, float* __restrict__ C,
    int M, int N, int K)
{
    const int BM = 128, BN = 64, BK = 16;
    __shared__ float As[BK][BM];
    __shared__ float Bs[BK][BN];

    int tid = threadIdx.x;
    int bm  = blockIdx.y * BM;
    int bn  = blockIdx.x * BN;
    int tx  = tid & 15;     // n dir, 4 cols each
    int ty  = tid >> 4;     // m dir, 8 rows each

    float acc[8][4];
#pragma unroll
    for (int i = 0; i < 8; i++)
#pragma unroll
        for (int j = 0; j < 4; j++) acc[i][j] = 0.f;

    int arow = tid >> 2;          // 0..63
    int acol = (tid & 3) * 4;     // 0,4,8,12
    int brow = tid >> 4;          // 0..15
    int bcol = (tid & 15) * 4;

    for (int k0 = 0; k0 < K; k0 += BK) {
        float4 a0 = *(const float4*)&A[(size_t)(bm + arow)      * K + k0 + acol];
        float4 a1 = *(const float4*)&A[(size_t)(bm + arow + 64) * K + k0 + acol];
        float4 bv = *(const float4*)&B[(size_t)(k0 + brow) * N + bn + bcol];
        __syncthreads();
        As[acol + 0][arow]      = a0.x;
        As[acol + 1][arow]      = a0.y;
        As[acol + 2][arow]      = a0.z;
        As[acol + 3][arow]      = a0.w;
        As[acol + 0][arow + 64] = a1.x;
        As[acol + 1][arow + 64] = a1.y;
        As[acol + 2][arow + 64] = a1.z;
        As[acol + 3][arow + 64] = a1.w;
        *(float4*)&Bs[brow][bcol] = bv;
        __syncthreads();
#pragma unroll
        for (int kk = 0; kk < BK; kk++) {
            float am[8], bb[4];
            *(float4*)&am[0] = *(const float4*)&As[kk][ty * 8];
            *(float4*)&am[4] = *(const float4*)&As[kk][ty * 8 + 4];
            *(float4*)&bb[0] = *(const float4*)&Bs[kk][tx * 4];
#pragma unroll
            for (int i = 0; i < 8; i++)
#pragma unroll
                for (int j = 0; j < 4; j++)
                    acc[i][j] += am[i] * bb[j];
        }
    }

#pragma unroll
    for (int i = 0; i < 8; i++) {
        size_t row = (size_t)(bm + ty * 8 + i);
#pragma unroll
        for (int j = 0; j < 4; j++) {
            int col = bn + tx * 4 + j;
            C[row * N + col] = acc[i][j] + bias[col];
        }
    }
}

// ---------------------------------------------------------------------------
// Persistent LSTM recurrence.
//   grid = 128 CTAs: blockIdx.x = g*16 + cb (g: batch group of 8 rows,
//   cb: column block owning NH = H/16 h-columns and their 4 gate columns).
//   U slice in smem (loaded once). c-state in registers. h_{t-1} read from the
//   layer's own output buffer; per-group flag counters gate each step.
// ---------------------------------------------------------------------------
template <int H>
__global__ __launch_bounds__(256) void lstm_rec(
    const float* __restrict__ zx,   // [B][T][4H]
    const float* __restrict__ U,    // [H][4H]
    float* __restrict__ out,        // [B][T][H]  (also h exchange buffer)
    int* __restrict__ flags)        // [G][T]
{
    constexpr int N4    = 4 * H;
    constexpr int G     = 8;           (void)G;
    constexpr int Bg    = 8;
    constexpr int Pc    = 16;
    constexpr int NH    = H / Pc;      // h cols per CTA (16 or 8)
    constexpr int NCZ   = 4 * NH;      // z cols per CTA (64 or 32)
    constexpr int CPAIR = NCZ / 2;     // 32 or 16
    constexpr int KSL   = 256 / CPAIR; // k slices (8 or 16)
    constexpr int KIT   = H / KSL;     // k iters per slice (32 or 8)
    constexpr int NRED  = Bg * NH;     // reduce threads (128 or 64)

    extern __shared__ float sm[];
    float* U_s = sm;                 // [H][NCZ], gate-major within block
    float* h_s = U_s + H * NCZ;      // [Bg][H] row-major
    float* zp  = h_s + Bg * H;       // [KSL][Bg][NCZ]

    int tid = threadIdx.x;
    int g   = blockIdx.x >> 4;
    int cb  = blockIdx.x & 15;
    int jb  = cb * NH;

    // Load U slice: columns {gi*H + jb + j : gi in 0..3, j in 0..NH-1}
    for (int idx = tid; idx < H * NCZ; idx += 256) {
        int k  = idx / NCZ;
        int c  = idx % NCZ;
        int gi = c / NH;
        int j  = c % NH;
        U_s[idx] = U[(size_t)k * N4 + gi * H + jb + j];
    }

    // Reduce-thread identity (valid when tid < NRED)
    int rr = tid / NH;
    int jj = tid % NH;
    int bglob = g * Bg + rr;
    float creg = 0.f;

    // Matmul-thread identity
    int cp = tid % CPAIR;
    int ks = tid / CPAIR;

    const int* flagrd = flags + g * T_STEPS;
    __syncthreads();

    for (int t = 0; t < T_STEPS; t++) {
        // Prefetch zx for this step (independent of h availability).
        float zx0 = 0.f, zx1 = 0.f, zx2 = 0.f, zx3 = 0.f;
        if (tid < NRED) {
            size_t base = ((size_t)bglob * T_STEPS + t) * N4 + jb + jj;
            zx0 = zx[base + 0 * (size_t)H];
            zx1 = zx[base + 1 * (size_t)H];
            zx2 = zx[base + 2 * (size_t)H];
            zx3 = zx[base + 3 * (size_t)H];
        }

        float z0 = 0.f, z1 = 0.f, z2 = 0.f, z3 = 0.f;
        if (t > 0) {
            // Wait until all 16 CTAs of this batch group published h_{t-1}.
            if (tid == 0) {
                while (((volatile int*)flagrd)[t - 1] < Pc) { }
            }
            __syncthreads();
            __threadfence();  // acquire

            // Load h_{t-1}[Bg][H] from global (our batch rows, all H cols).
            for (int i4 = tid; i4 < (Bg * H) / 4; i4 += 256) {
                int idx = i4 * 4;
                int r = idx / H, k = idx % H;
                float4 v = *(const float4*)&out[((size_t)(g * Bg + r) * T_STEPS + (t - 1)) * H + k];
                *(float4*)&h_s[idx] = v;
            }
            __syncthreads();

            // z_partial[Bg][NCZ] = h_s @ U_s, split-K across KSL slices.
            float acc0[8], acc1[8];
#pragma unroll
            for (int r = 0; r < 8; r++) { acc0[r] = 0.f; acc1[r] = 0.f; }
#pragma unroll 2
            for (int kk = 0; kk < KIT; kk += 4) {
                int k = ks * KIT + kk;
                float u0[4], u1[4];
#pragma unroll
                for (int q = 0; q < 4; q++) {
                    u0[q] = U_s[(k + q) * NCZ + cp];
                    u1[q] = U_s[(k + q) * NCZ + cp + CPAIR];
                }
#pragma unroll
                for (int r = 0; r < 8; r++) {
                    float4 hv = *(const float4*)&h_s[r * H + k];
                    acc0[r] += u0[0] * hv.x; acc1[r] += u1[0] * hv.x;
                    acc0[r] += u0[1] * hv.y; acc1[r] += u1[1] * hv.y;
                    acc0[r] += u0[2] * hv.z; acc1[r] += u1[2] * hv.z;
                    acc0[r] += u0[3] * hv.w; acc1[r] += u1[3] * hv.w;
                }
            }
#pragma unroll
            for (int r = 0; r < 8; r++) {
                zp[(ks * Bg + r) * NCZ + cp]         = acc0[r];
                zp[(ks * Bg + r) * NCZ + cp + CPAIR] = acc1[r];
            }
            __syncthreads();

            if (tid < NRED) {
#pragma unroll
                for (int s = 0; s < KSL; s++) {
                    const float* zrow = &zp[(s * Bg + rr) * NCZ];
                    z0 += zrow[0 * NH + jj];
                    z1 += zrow[1 * NH + jj];
                    z2 += zrow[2 * NH + jj];
                    z3 += zrow[3 * NH + jj];
                }
            }
        }

        // Gates + state update + publish h_t.
        if (tid < NRED) {
            float zi = zx0 + z0, zf = zx1 + z1, zg = zx2 + z2, zo = zx3 + z3;
            float si = 1.f / (1.f + __expf(-zi));
            float sf = 1.f / (1.f + __expf(-zf));
            float so = 1.f / (1.f + __expf(-zo));
            float gg = zg > 0.f ? zg : 0.f;
            creg = sf * creg + si * gg;
            float cr = creg > 0.f ? creg : 0.f;
            out[((size_t)bglob * T_STEPS + t) * H + jb + jj] = so * cr;
        }
        __threadfence();   // release (every thread fences its own stores)
        __syncthreads();
        if (tid == 0) atomicAdd(&flags[g * T_STEPS + t], 1);
    }
}

// ---------------------------------------------------------------------------
// Launch: 4 x (GEMM -> flag reset -> recurrence), all on the default stream.
// ---------------------------------------------------------------------------
extern "C" void kernel_launch(void* const* d_in, const int* in_sizes, int n_in,
                              void* d_out, int out_size)
{
    const float* x  = (const float*)d_in[0];
    const float* W1 = (const float*)d_in[1];
    const float* U1 = (const float*)d_in[2];
    const float* b1 = (const float*)d_in[3];
    const float* W2 = (const float*)d_in[4];
    const float* U2 = (const float*)d_in[5];
    const float* b2 = (const float*)d_in[6];
    const float* W3 = (const float*)d_in[7];
    const float* U3 = (const float*)d_in[8];
    const float* b3 = (const float*)d_in[9];
    const float* W4 = (const float*)d_in[10];
    const float* U4 = (const float*)d_in[11];
    const float* b4 = (const float*)d_in[12];
    float* out = (float*)d_out;

    void *zx_p, *bufA_p, *bufB_p, *flags_p;
    cudaGetSymbolAddress(&zx_p,    g_zx);
    cudaGetSymbolAddress(&bufA_p,  g_bufA);
    cudaGetSymbolAddress(&bufB_p,  g_bufB);
    cudaGetSymbolAddress(&flags_p, g_flags);
    float* zx   = (float*)zx_p;
    float* bufA = (float*)bufA_p;
    float* bufB = (float*)bufB_p;
    int*   flags = (int*)flags_p;

    const int M = BATCH * T_STEPS;  // 65536

    // smem sizes for the recurrence kernels
    const int SMEM256 = (256 * 64 + 8 * 256 + 8 * 8 * 64) * 4;    // 90112 B
    const int SMEM128 = (128 * 32 + 8 * 128 + 16 * 8 * 32) * 4;   // 36864 B
    cudaFuncSetAttribute((const void*)lstm_rec<256>,
                         cudaFuncAttributeMaxDynamicSharedMemorySize, SMEM256);
    cudaFuncSetAttribute((const void*)lstm_rec<128>,
                         cudaFuncAttributeMaxDynamicSharedMemorySize, SMEM128);

    const size_t FLAGS_BYTES = 8 * T_STEPS * sizeof(int);

    // ---- Layer 1: F=256 -> H=256 ----
    sgemm_bias<<<dim3(1024 / 64, M / 128), 256>>>(x, W1, b1, zx, M, 1024, 256);
    cudaMemsetAsync(flags, 0, FLAGS_BYTES);
    lstm_rec<256><<<128, 256, SMEM256>>>(zx, U1, bufA, flags);

    // ---- Layer 2: F=256 -> H=128 ----
    sgemm_bias<<<dim3(512 / 64, M / 128), 256>>>(bufA, W2, b2, zx, M, 512, 256);
    cudaMemsetAsync(flags, 0, FLAGS_BYTES);
    lstm_rec<128><<<128, 256, SMEM128>>>(zx, U2, bufB, flags);

    // ---- Layer 3: F=128 -> H=256 ----
    sgemm_bias<<<dim3(1024 / 64, M / 128), 256>>>(bufB, W3, b3, zx, M, 1024, 128);
    cudaMemsetAsync(flags, 0, FLAGS_BYTES);
    lstm_rec<256><<<128, 256, SMEM256>>>(zx, U3, bufA, flags);

    // ---- Layer 4: F=256 -> H=256 ----
    sgemm_bias<<<dim3(1024 / 64, M / 128), 256>>>(bufA, W4, b4, zx, M, 1024, 256);
    cudaMemsetAsync(flags, 0, FLAGS_BYTES);
    lstm_rec<256><<<128, 256, SMEM256>>>(zx, U4, out, flags);
}

// round 2
// speedup vs baseline: 1.0960x; 1.0960x over previous
#include <cuda_runtime.h>
#include <cstdint>

// ---------------------------------------------------------------------------
// LSTM autoencoder: 4 layers, B=64, T=1024, H in {256,128,256,256}.
//   1) sgemm_bias: zx[b][t][4H] = x[b][t][:] @ W + b   (128x128x8 fp32 GEMM)
//   2) lstm_rec:   persistent 128-CTA kernel, 8 batch groups x 16 col CTAs,
//      CG-style release/acquire flag sync per step (tid0-only fences).
// ---------------------------------------------------------------------------

#define T_STEPS 1024
#define BATCH   64

// Scratch (device globals: allocation-free rule)
__device__ float g_zx[67108864];        // [B*T][4*256] max
__device__ float g_bufA[16777216];      // [B][T][256]
__device__ float g_bufB[8388608];       // [B][T][128]
__device__ int   g_flags[4 * 8 * T_STEPS]; // [layer][G][T]

// -------------------- sync primitives (CG grid-sync idiom) -----------------
__device__ __forceinline__ int ld_acquire_gpu(const int* p) {
    int v;
    asm volatile("ld.acquire.gpu.global.s32 %0, [%1];" : "=r"(v) : "l"(p) : "memory");
    return v;
}
__device__ __forceinline__ void red_release_gpu_add(int* p, int v) {
    asm volatile("red.release.gpu.global.add.s32 [%0], %1;" :: "l"(p), "r"(v) : "memory");
}

// ---------------------------------------------------------------------------
// GEMM: C[m][n] = sum_k A[m][k]*B[k][n] + bias[n]
// BM=128, BN=128, BK=8, 256 threads, 8x8 microtile.
// Requires M%128==0, N%128==0, K%8==0 (true for all 4 layers).
// ---------------------------------------------------------------------------
__global__ __launch_bounds__(256) void sgemm_bias(
    const float* __restrict__ A, const float* __restrict__ B,
    const float* __restrict__ bias, float* __restrict__ C,
    int M, int N, int K)
{
    const int BM = 128, BN = 128, BK = 8;
    __shared__ float As[BK][BM];
    __shared__ float Bs[BK][BN];

    int tid = threadIdx.x;
    int bm  = blockIdx.y * BM;
    int bn  = blockIdx.x * BN;
    int tx  = tid & 15;     // n dir, 8 cols each
    int ty  = tid >> 4;     // m dir, 8 rows each

    float acc[8][8];
#pragma unroll
    for (int i = 0; i < 8; i++)
#pragma unroll
        for (int j = 0; j < 8; j++) acc[i][j] = 0.f;

    int aRow = tid >> 1;          // 0..127
    int aCol = (tid & 1) * 4;     // 0 or 4
    int bRow = tid >> 5;          // 0..7
    int bCol = (tid & 31) * 4;    // 0..124

    const float* Aptr = A + (size_t)(bm + aRow) * K;

    for (int k0 = 0; k0 < K; k0 += BK) {
        float4 av = *(const float4*)&Aptr[k0 + aCol];
        float4 bv = *(const float4*)&B[(size_t)(k0 + bRow) * N + bn + bCol];
        __syncthreads();
        As[aCol + 0][aRow] = av.x;
        As[aCol + 1][aRow] = av.y;
        As[aCol + 2][aRow] = av.z;
        As[aCol + 3][aRow] = av.w;
        *(float4*)&Bs[bRow][bCol] = bv;
        __syncthreads();
#pragma unroll
        for (int kk = 0; kk < BK; kk++) {
            float a[8], b[8];
            *(float4*)&a[0] = *(const float4*)&As[kk][ty * 8];
            *(float4*)&a[4] = *(const float4*)&As[kk][ty * 8 + 4];
            *(float4*)&b[0] = *(const float4*)&Bs[kk][tx * 8];
            *(float4*)&b[4] = *(const float4*)&Bs[kk][tx * 8 + 4];
#pragma unroll
            for (int i = 0; i < 8; i++)
#pragma unroll
                for (int j = 0; j < 8; j++)
                    acc[i][j] += a[i] * b[j];
        }
    }

#pragma unroll
    for (int i = 0; i < 8; i++) {
        size_t row = (size_t)(bm + ty * 8 + i);
#pragma unroll
        for (int j = 0; j < 8; j += 4) {
            int col = bn + tx * 8 + j;
            float4 o;
            o.x = acc[i][j + 0] + bias[col + 0];
            o.y = acc[i][j + 1] + bias[col + 1];
            o.z = acc[i][j + 2] + bias[col + 2];
            o.w = acc[i][j + 3] + bias[col + 3];
            *(float4*)&C[row * N + col] = o;
        }
    }
}

// ---------------------------------------------------------------------------
// Persistent LSTM recurrence.
//   grid = 128 CTAs: blockIdx.x = g*16 + cb (g: batch group of 8 rows,
//   cb: column CTA owning NH = H/16 h-columns and their 4 gate columns).
//   U slice in smem (loaded once). c-state in registers. h exchanged through
//   the layer output buffer in L2; per-group flag counters gate each step.
// ---------------------------------------------------------------------------
template <int H>
__global__ __launch_bounds__(256) void lstm_rec(
    const float* __restrict__ zx,   // [B][T][4H]
    const float* __restrict__ U,    // [H][4H]
    float* __restrict__ out,        // [B][T][H]  (also h exchange buffer)
    int* __restrict__ flags)        // [G][T]
{
    constexpr int N4    = 4 * H;
    constexpr int Bg    = 8;
    constexpr int Pc    = 16;
    constexpr int NH    = H / Pc;      // h cols per CTA (16 or 8)
    constexpr int NCZ   = 4 * NH;      // z cols per CTA (64 or 32)
    constexpr int CPAIR = NCZ / 2;     // 32 or 16
    constexpr int KSL   = 256 / CPAIR; // k slices (8 or 16)
    constexpr int KIT   = H / KSL;     // k iters per slice (32 or 8)
    constexpr int NRED  = Bg * NH;     // reduce threads (128 or 64)

    extern __shared__ float sm[];
    float* U_s = sm;                 // [H][NCZ], gate-major within block
    float* h_s = U_s + H * NCZ;      // [Bg][H] row-major
    float* zp  = h_s + Bg * H;       // [KSL][Bg][NCZ]

    int tid = threadIdx.x;
    int g   = blockIdx.x >> 4;
    int cb  = blockIdx.x & 15;
    int jb  = cb * NH;

    // Load U slice: columns {gi*H + jb + j : gi in 0..3, j in 0..NH-1}
    for (int idx = tid; idx < H * NCZ; idx += 256) {
        int k  = idx / NCZ;
        int c  = idx % NCZ;
        int gi = c / NH;
        int j  = c % NH;
        U_s[idx] = U[(size_t)k * N4 + gi * H + jb + j];
    }

    // Reduce-thread identity (valid when tid < NRED)
    int rr = tid / NH;
    int jj = tid % NH;
    int bglob = g * Bg + rr;
    float creg = 0.f;

    // Matmul-thread identity
    int cp = tid % CPAIR;
    int ks = tid / CPAIR;

    int* flagrd = flags + g * T_STEPS;
    __syncthreads();

    for (int t = 0; t < T_STEPS; t++) {
        // Prefetch zx for this step (independent of h availability).
        float zx0 = 0.f, zx1 = 0.f, zx2 = 0.f, zx3 = 0.f;
        if (tid < NRED) {
            size_t base = ((size_t)bglob * T_STEPS + t) * N4 + jb + jj;
            zx0 = zx[base + 0 * (size_t)H];
            zx1 = zx[base + 1 * (size_t)H];
            zx2 = zx[base + 2 * (size_t)H];
            zx3 = zx[base + 3 * (size_t)H];
        }

        float z0 = 0.f, z1 = 0.f, z2 = 0.f, z3 = 0.f;
        if (t > 0) {
            // Acquire: wait until all 16 CTAs of this group published h_{t-1}.
            if (tid == 0) {
                while (ld_acquire_gpu(&flagrd[t - 1]) < Pc) { }
            }
            __syncthreads();

            // Load h_{t-1}[Bg][H] from global (our batch rows, all H cols).
            for (int i4 = tid; i4 < (Bg * H) / 4; i4 += 256) {
                int idx = i4 * 4;
                int r = idx / H, k = idx % H;
                float4 v = *(const float4*)&out[((size_t)(g * Bg + r) * T_STEPS + (t - 1)) * H + k];
                *(float4*)&h_s[idx] = v;
            }
            __syncthreads();

            // z_partial[Bg][NCZ] = h_s @ U_s, split-K across KSL slices.
            float acc0[8], acc1[8];
#pragma unroll
            for (int r = 0; r < 8; r++) { acc0[r] = 0.f; acc1[r] = 0.f; }
#pragma unroll 2
            for (int kk = 0; kk < KIT; kk += 4) {
                int k = ks * KIT + kk;
                float u0[4], u1[4];
#pragma unroll
                for (int q = 0; q < 4; q++) {
                    u0[q] = U_s[(k + q) * NCZ + cp];
                    u1[q] = U_s[(k + q) * NCZ + cp + CPAIR];
                }
#pragma unroll
                for (int r = 0; r < 8; r++) {
                    float4 hv = *(const float4*)&h_s[r * H + k];
                    acc0[r] += u0[0] * hv.x; acc1[r] += u1[0] * hv.x;
                    acc0[r] += u0[1] * hv.y; acc1[r] += u1[1] * hv.y;
                    acc0[r] += u0[2] * hv.z; acc1[r] += u1[2] * hv.z;
                    acc0[r] += u0[3] * hv.w; acc1[r] += u1[3] * hv.w;
                }
            }
#pragma unroll
            for (int r = 0; r < 8; r++) {
                zp[(ks * Bg + r) * NCZ + cp]         = acc0[r];
                zp[(ks * Bg + r) * NCZ + cp + CPAIR] = acc1[r];
            }
            __syncthreads();

            if (tid < NRED) {
#pragma unroll
                for (int s = 0; s < KSL; s++) {
                    const float* zrow = &zp[(s * Bg + rr) * NCZ];
                    z0 += zrow[0 * NH + jj];
                    z1 += zrow[1 * NH + jj];
                    z2 += zrow[2 * NH + jj];
                    z3 += zrow[3 * NH + jj];
                }
            }
        }

        // Gates + state update + publish h_t.
        if (tid < NRED) {
            float zi = zx0 + z0, zf = zx1 + z1, zg = zx2 + z2, zo = zx3 + z3;
            float si = 1.f / (1.f + __expf(-zi));
            float sf = 1.f / (1.f + __expf(-zf));
            float so = 1.f / (1.f + __expf(-zo));
            float gg = zg > 0.f ? zg : 0.f;
            creg = sf * creg + si * gg;
            float cr = creg > 0.f ? creg : 0.f;
            out[((size_t)bglob * T_STEPS + t) * H + jb + jj] = so * cr;
        }
        __syncthreads();
        // Release: tid0 publishes (release red covers peer stores via bar.sync,
        // same idiom as cooperative_groups grid sync).
        if (tid == 0) red_release_gpu_add(&flags[g * T_STEPS + t], 1);
        // NOTE: no trailing barrier needed; next iteration's use of shared
        // buffers is guarded by its own __syncthreads() after the flag wait.
        __syncthreads();
    }
}

// ---------------------------------------------------------------------------
extern "C" void kernel_launch(void* const* d_in, const int* in_sizes, int n_in,
                              void* d_out, int out_size)
{
    const float* x  = (const float*)d_in[0];
    const float* W1 = (const float*)d_in[1];
    const float* U1 = (const float*)d_in[2];
    const float* b1 = (const float*)d_in[3];
    const float* W2 = (const float*)d_in[4];
    const float* U2 = (const float*)d_in[5];
    const float* b2 = (const float*)d_in[6];
    const float* W3 = (const float*)d_in[7];
    const float* U3 = (const float*)d_in[8];
    const float* b3 = (const float*)d_in[9];
    const float* W4 = (const float*)d_in[10];
    const float* U4 = (const float*)d_in[11];
    const float* b4 = (const float*)d_in[12];
    float* out = (float*)d_out;

    void *zx_p, *bufA_p, *bufB_p, *flags_p;
    cudaGetSymbolAddress(&zx_p,    g_zx);
    cudaGetSymbolAddress(&bufA_p,  g_bufA);
    cudaGetSymbolAddress(&bufB_p,  g_bufB);
    cudaGetSymbolAddress(&flags_p, g_flags);
    float* zx    = (float*)zx_p;
    float* bufA  = (float*)bufA_p;
    float* bufB  = (float*)bufB_p;
    int*   flags = (int*)flags_p;

    const int M = BATCH * T_STEPS;  // 65536

    const int SMEM256 = (256 * 64 + 8 * 256 + 8 * 8 * 64) * 4;    // 90112 B
    const int SMEM128 = (128 * 32 + 8 * 128 + 16 * 8 * 32) * 4;   // 36864 B
    cudaFuncSetAttribute((const void*)lstm_rec<256>,
                         cudaFuncAttributeMaxDynamicSharedMemorySize, SMEM256);
    cudaFuncSetAttribute((const void*)lstm_rec<128>,
                         cudaFuncAttributeMaxDynamicSharedMemorySize, SMEM128);

    // Zero all 4 layers' flags once.
    cudaMemsetAsync(flags, 0, 4 * 8 * T_STEPS * sizeof(int));

    // ---- Layer 1: F=256 -> H=256 ----
    sgemm_bias<<<dim3(1024 / 128, M / 128), 256>>>(x, W1, b1, zx, M, 1024, 256);
    lstm_rec<256><<<128, 256, SMEM256>>>(zx, U1, bufA, flags + 0 * 8 * T_STEPS);

    // ---- Layer 2: F=256 -> H=128 ----
    sgemm_bias<<<dim3(512 / 128, M / 128), 256>>>(bufA, W2, b2, zx, M, 512, 256);
    lstm_rec<128><<<128, 256, SMEM128>>>(zx, U2, bufB, flags + 1 * 8 * T_STEPS);

    // ---- Layer 3: F=128 -> H=256 ----
    sgemm_bias<<<dim3(1024 / 128, M / 128), 256>>>(bufB, W3, b3, zx, M, 1024, 128);
    lstm_rec<256><<<128, 256, SMEM256>>>(zx, U3, bufA, flags + 2 * 8 * T_STEPS);

    // ---- Layer 4: F=256 -> H=256 ----
    sgemm_bias<<<dim3(1024 / 128, M / 128), 256>>>(bufA, W4, b4, zx, M, 1024, 256);
    lstm_rec<256><<<128, 256, SMEM256>>>(zx, U4, out, flags + 3 * 8 * T_STEPS);
}